// round 5
// baseline (speedup 1.0000x reference)
#include <cuda_runtime.h>
#include <math.h>

#define NN    4096
#define EE    131072
#define ETOT  (EE + NN)
#define NEG_SLOPE 0.2f

// ---- scratch: zero-initialized at module load; every launch restores zeros at exit ----
__device__ float4             g_nA[NN];       // {acc0, acc1, acc2, ssum} layer 1
__device__ float4             g_nB[NN];       // {acc0, acc1, acc2, ssum} layer 2
__device__ float2             g_n3[NN];       // {acc, ssum} layer 3
__device__ float              g_xf[NN];       // fully overwritten each launch
__device__ unsigned long long g_ckey[NN];     // zeroed by walk block after reading
__device__ float              g_p12;          // overwritten each launch
__device__ int                g_start;        // overwritten each launch
__device__ unsigned           g_done3;        // edge3 completion counter (self-resetting)
__device__ unsigned           g_doneC;        // ckey completion counter (self-resetting)

__device__ __forceinline__ unsigned int fenc(float f) {
    unsigned int u = __float_as_uint(f);
    return (u & 0x80000000u) ? ~u : (u | 0x80000000u);
}
__device__ __forceinline__ float leaky(float x) { return x >= 0.0f ? x : NEG_SLOPE * x; }
__device__ __forceinline__ float relu(float x)  { return x > 0.0f ? x : 0.0f; }

// -------- kernel 1: layer-1 edge pass (z1 recomputed on the fly from x) --------
__global__ void k_edge1(const float* __restrict__ x, const int* __restrict__ ei,
                        const float* __restrict__ W1, const float* __restrict__ as1,
                        const float* __restrict__ ad1) {
    int t = blockIdx.x * blockDim.x + threadIdx.x;
    if (t >= ETOT) return;
    int s, d;
    if (t < EE) { s = __ldg(ei + t); d = __ldg(ei + EE + t); } else { s = t - EE; d = s; }
    float xs = __ldg(x + s), xd = __ldg(x + d);
    float zs = 0.f, zd = 0.f, z[3];
#pragma unroll
    for (int k = 0; k < 3; k++) {
        float w1k = __ldg(W1 + k);
        z[k] = xs * w1k;
        zs += z[k] * __ldg(as1 + k);
        zd += (xd * w1k) * __ldg(ad1 + k);
    }
    float w = __expf(leaky(zs + zd));            // softmax shift-invariant: no segment max
    atomicAdd(&g_nA[d].x, w * z[0]);
    atomicAdd(&g_nA[d].y, w * z[1]);
    atomicAdd(&g_nA[d].z, w * z[2]);
    atomicAdd(&g_nA[d].w, w);
}

// layer-2 feature from layer-1 accumulators (one LDG.128)
__device__ __forceinline__ void z2_of(int n, const float* b1r, const float* W2r, float* z2) {
    float4 a = g_nA[n];
    float inv = 1.0f / (a.w + 1e-16f);
    float h0 = relu(a.x * inv + b1r[0]);
    float h1 = relu(a.y * inv + b1r[1]);
    float h2 = relu(a.z * inv + b1r[2]);
#pragma unroll
    for (int k = 0; k < 3; k++)
        z2[k] = h0 * W2r[k * 3 + 0] + h1 * W2r[k * 3 + 1] + h2 * W2r[k * 3 + 2];
}

// -------- kernel 2: layer-2 edge pass --------
__global__ void k_edge2(const int* __restrict__ ei, const float* __restrict__ b1,
                        const float* __restrict__ W2, const float* __restrict__ as2,
                        const float* __restrict__ ad2) {
    int t = blockIdx.x * blockDim.x + threadIdx.x;
    if (t >= ETOT) return;
    float b1r[3], W2r[9];
#pragma unroll
    for (int k = 0; k < 3; k++) b1r[k] = __ldg(b1 + k);
#pragma unroll
    for (int k = 0; k < 9; k++) W2r[k] = __ldg(W2 + k);
    int s, d;
    if (t < EE) { s = __ldg(ei + t); d = __ldg(ei + EE + t); } else { s = t - EE; d = s; }
    float zS[3], zD[3];
    z2_of(s, b1r, W2r, zS);
    z2_of(d, b1r, W2r, zD);
    float zs = 0.f, zd = 0.f;
#pragma unroll
    for (int k = 0; k < 3; k++) { zs += zS[k] * __ldg(as2 + k); zd += zD[k] * __ldg(ad2 + k); }
    float w = __expf(leaky(zs + zd));
    atomicAdd(&g_nB[d].x, w * zS[0]);
    atomicAdd(&g_nB[d].y, w * zS[1]);
    atomicAdd(&g_nB[d].z, w * zS[2]);
    atomicAdd(&g_nB[d].w, w);
}

__device__ __forceinline__ float z3_of(int n, const float* b2r, const float* W3r) {
    float4 a = g_nB[n];
    float inv = 1.0f / (a.w + 1e-16f);
    return relu(a.x * inv + b2r[0]) * W3r[0]
         + relu(a.y * inv + b2r[1]) * W3r[1]
         + relu(a.z * inv + b2r[2]) * W3r[2];
}

// -------- kernel 3: layer-3 edge pass; LAST block computes softmax+argmax+p12 --------
__global__ void k_edge3(const int* __restrict__ ei, const float* __restrict__ b2,
                        const float* __restrict__ W3, const float* __restrict__ as3,
                        const float* __restrict__ ad3, const float* __restrict__ b3,
                        const float* __restrict__ phi1, const float* __restrict__ phi2,
                        float* __restrict__ out) {
    int t = blockIdx.x * blockDim.x + threadIdx.x;
    if (t < ETOT) {
        float b2r[3], W3r[3];
#pragma unroll
        for (int k = 0; k < 3; k++) { b2r[k] = __ldg(b2 + k); W3r[k] = __ldg(W3 + k); }
        int s, d;
        if (t < EE) { s = __ldg(ei + t); d = __ldg(ei + EE + t); } else { s = t - EE; d = s; }
        float zS = z3_of(s, b2r, W3r);
        float zD = z3_of(d, b2r, W3r);
        float w = __expf(leaky(zS * __ldg(as3) + zD * __ldg(ad3)));
        atomicAdd(&g_n3[d].x, w * zS);
        atomicAdd(&g_n3[d].y, w);
    }

    // ---- last-finishing block does the node softmax ----
    __shared__ unsigned isLast;
    __threadfence();
    __syncthreads();
    if (threadIdx.x == 0)
        isLast = (atomicAdd(&g_done3, 1u) == (unsigned)(gridDim.x - 1)) ? 1u : 0u;
    __syncthreads();
    if (!isLast) return;

    {
        const int tid = threadIdx.x;                 // 256 threads, 16 nodes each
        __shared__ float sred[8];
        __shared__ unsigned long long skey[8];
        __shared__ float s_sum;
        float b = __ldg(b3);
        float wv[16];
        float lsum = 0.f;
#pragma unroll
        for (int r = 0; r < 16; r++) {
            int i = r * 256 + tid;
            float2 a = __ldcg(&g_n3[i]);
            float o = a.x / (a.y + 1e-16f) + b;
            wv[r] = __expf(o);
            lsum += wv[r];
        }
        // block sum via shuffles
#pragma unroll
        for (int off = 16; off > 0; off >>= 1) lsum += __shfl_down_sync(0xFFFFFFFFu, lsum, off);
        if ((tid & 31) == 0) sred[tid >> 5] = lsum;
        __syncthreads();
        if (tid < 32) {
            float v = (tid < 8) ? sred[tid] : 0.f;
#pragma unroll
            for (int off = 4; off > 0; off >>= 1) v += __shfl_down_sync(0xFFFFFFFFu, v, off);
            if (tid == 0) s_sum = v;
        }
        __syncthreads();
        float inv = 1.0f / s_sum;

        unsigned long long lkey = 0ull;
#pragma unroll
        for (int r = 0; r < 16; r++) {
            int i = r * 256 + tid;
            float xo = wv[r] * inv;
            out[i]  = xo;
            g_xf[i] = xo;
            unsigned long long k =
                ((unsigned long long)fenc(xo) << 32) | (unsigned long long)(0xFFFFFFFFu - (unsigned)i);
            if (k > lkey) lkey = k;
        }
#pragma unroll
        for (int off = 16; off > 0; off >>= 1) {
            unsigned long long o2 = __shfl_down_sync(0xFFFFFFFFu, lkey, off);
            if (o2 > lkey) lkey = o2;
        }
        if ((tid & 31) == 0) skey[tid >> 5] = lkey;
        __syncthreads();

        // p12 = dot(phi1, phi2) over 128 by warp 1 meanwhile; warp 0 finishes key
        if (tid < 32) {
            unsigned long long v = (tid < 8) ? skey[tid] : 0ull;
#pragma unroll
            for (int off = 4; off > 0; off >>= 1) {
                unsigned long long o2 = __shfl_down_sync(0xFFFFFFFFu, v, off);
                if (o2 > v) v = o2;
            }
            if (tid == 0) g_start = (int)(0xFFFFFFFFu - (unsigned)(v & 0xFFFFFFFFull));
        } else if (tid >= 32 && tid < 64) {
            int l = tid - 32;
            float p = 0.f;
#pragma unroll
            for (int k = 0; k < 4; k++) p += __ldg(phi1 + l + 32 * k) * __ldg(phi2 + l + 32 * k);
#pragma unroll
            for (int off = 16; off > 0; off >>= 1) p += __shfl_down_sync(0xFFFFFFFFu, p, off);
            if (l == 0) g_p12 = p;
        }
        if (tid == 0) g_done3 = 0;                   // reset for next launch
    }
}

// -------- kernel 4: chain keys; zero dead accumulators; LAST block does the walk --------
__global__ void k_ckey(const int* __restrict__ ei, float* __restrict__ out, int out_size) {
    int j = blockIdx.x * blockDim.x + threadIdx.x;   // 0..EE-1 exactly
    {
        int s = __ldg(ei + j), d = __ldg(ei + EE + j);
        const float scale = 1.0f / sqrtf(128.0f);
        float t = ((g_p12 * g_xf[s]) * g_xf[d]) * scale;  // match reference mul order
        float sc = tanhf(t);                               // CONST == 1.0
        unsigned long long key =
            ((unsigned long long)fenc(sc) << 32) | (unsigned long long)(0xFFFFFFFFu - (unsigned)j);
        atomicMax(&g_ckey[s], key);
    }
    // restore all-zeros invariant (dead data): nA (NN*4), nB (NN*4), n3 (NN*2) floats
    if (j < NN * 4)               ((float*)g_nA)[j] = 0.f;
    else if (j < NN * 8)          ((float*)g_nB)[j - NN * 4] = 0.f;
    else if (j < NN * 10)         ((float*)g_n3)[j - NN * 8] = 0.f;

    // ---- last-finishing block resolves next[] and pointer-doubles the walk ----
    __shared__ unsigned isLast;
    __threadfence();
    __syncthreads();
    if (threadIdx.x == 0)
        isLast = (atomicAdd(&g_doneC, 1u) == (unsigned)(gridDim.x - 1)) ? 1u : 0u;
    __syncthreads();
    if (!isLast) return;

    {
        __shared__ int A[NN];
        __shared__ int B[NN];
        const int tid = threadIdx.x;                 // 256 threads, 16 each
#pragma unroll
        for (int r = 0; r < 16; r++) {
            int i = r * 256 + tid;
            unsigned long long key = __ldcg(&g_ckey[i]);
            g_ckey[i] = 0ull;                        // reset for next launch
            int jj = key ? (int)(0xFFFFFFFFu - (unsigned)(key & 0xFFFFFFFFull)) : 0;
            A[i] = __ldg(ei + EE + jj);
        }
        __syncthreads();
        for (int it = 0; it < 12; it++) {            // next^(2^12) = next^4096
#pragma unroll
            for (int r = 0; r < 16; r++) { int i = r * 256 + tid; B[i] = A[A[i]]; }
            __syncthreads();
#pragma unroll
            for (int r = 0; r < 16; r++) { int i = r * 256 + tid; A[i] = B[i]; }
            __syncthreads();
        }
        if (tid == 0) {
            if (out_size > NN) out[NN] = (float)A[g_start];
            g_doneC = 0;                             // reset for next launch
        }
    }
}

// ---------------- launch ----------------
extern "C" void kernel_launch(void* const* d_in, const int* in_sizes, int n_in,
                              void* d_out, int out_size) {
    const float* x    = (const float*)d_in[0];
    const int*   ei   = (const int*)  d_in[1];
    const float* W1   = (const float*)d_in[2];
    const float* as1  = (const float*)d_in[3];
    const float* ad1  = (const float*)d_in[4];
    const float* b1   = (const float*)d_in[5];
    const float* W2   = (const float*)d_in[6];
    const float* as2  = (const float*)d_in[7];
    const float* ad2  = (const float*)d_in[8];
    const float* b2   = (const float*)d_in[9];
    const float* W3   = (const float*)d_in[10];
    const float* as3  = (const float*)d_in[11];
    const float* ad3  = (const float*)d_in[12];
    const float* b3   = (const float*)d_in[13];
    const float* phi1 = (const float*)d_in[14];
    const float* phi2 = (const float*)d_in[15];
    float* out = (float*)d_out;

    const int NB_E = (ETOT + 255) / 256;   // 528
    const int NB_C = EE / 256;             // 512

    k_edge1<<<NB_E, 256>>>(x, ei, W1, as1, ad1);
    k_edge2<<<NB_E, 256>>>(ei, b1, W2, as2, ad2);
    k_edge3<<<NB_E, 256>>>(ei, b2, W3, as3, ad3, b3, phi1, phi2, out);
    k_ckey <<<NB_C, 256>>>(ei, out, out_size);
}

// round 6
// speedup vs baseline: 1.3639x; 1.3639x over previous
#include <cuda_runtime.h>
#include <math.h>

#define NN    4096
#define EE    131072
#define ETOT  (EE + NN)          // 135168 = 132 * 1024
#define NEG_SLOPE 0.2f
#define TB    1024
#define NB_E  (ETOT / TB)        // 132
#define NB_C  (EE / TB)          // 128

// ---- scratch: zero-initialized at module load; every launch restores zeros at exit ----
__device__ float4             g_nA[NN];       // {acc0, acc1, acc2, ssum} layer 1
__device__ float4             g_nB[NN];       // {acc0, acc1, acc2, ssum} layer 2
__device__ float2             g_n3[NN];       // {acc, ssum} layer 3
__device__ float              g_xf[NN];       // fully overwritten each launch
__device__ unsigned long long g_ckey[NN];     // zeroed by walk tail after reading
__device__ float              g_p12;          // overwritten each launch
__device__ int                g_start;        // overwritten each launch
__device__ unsigned           g_done3;        // edge3 completion counter (self-resetting)
__device__ unsigned           g_doneC;        // ckey completion counter (self-resetting)

__device__ __forceinline__ unsigned int fenc(float f) {
    unsigned int u = __float_as_uint(f);
    return (u & 0x80000000u) ? ~u : (u | 0x80000000u);
}
__device__ __forceinline__ float leaky(float x) { return x >= 0.0f ? x : NEG_SLOPE * x; }
__device__ __forceinline__ float relu(float x)  { return x > 0.0f ? x : 0.0f; }

// -------- kernel 1: layer-1 edge pass (z1 recomputed on the fly from x) --------
__global__ void __launch_bounds__(TB)
k_edge1(const float* __restrict__ x, const int* __restrict__ ei,
        const float* __restrict__ W1, const float* __restrict__ as1,
        const float* __restrict__ ad1) {
    int t = blockIdx.x * TB + threadIdx.x;          // always < ETOT (exact grid)
    int s, d;
    if (t < EE) { s = __ldg(ei + t); d = __ldg(ei + EE + t); } else { s = t - EE; d = s; }
    float xs = __ldg(x + s), xd = __ldg(x + d);
    float zs = 0.f, zd = 0.f, z[3];
#pragma unroll
    for (int k = 0; k < 3; k++) {
        float w1k = __ldg(W1 + k);
        z[k] = xs * w1k;
        zs += z[k] * __ldg(as1 + k);
        zd += (xd * w1k) * __ldg(ad1 + k);
    }
    float w = __expf(leaky(zs + zd));               // softmax shift-invariant: no segment max
    atomicAdd(&g_nA[d].x, w * z[0]);
    atomicAdd(&g_nA[d].y, w * z[1]);
    atomicAdd(&g_nA[d].z, w * z[2]);
    atomicAdd(&g_nA[d].w, w);
}

// layer-2 feature from layer-1 accumulators (one LDG.128)
__device__ __forceinline__ void z2_of(int n, const float* b1r, const float* W2r, float* z2) {
    float4 a = g_nA[n];
    float inv = 1.0f / (a.w + 1e-16f);
    float h0 = relu(a.x * inv + b1r[0]);
    float h1 = relu(a.y * inv + b1r[1]);
    float h2 = relu(a.z * inv + b1r[2]);
#pragma unroll
    for (int k = 0; k < 3; k++)
        z2[k] = h0 * W2r[k * 3 + 0] + h1 * W2r[k * 3 + 1] + h2 * W2r[k * 3 + 2];
}

// -------- kernel 2: layer-2 edge pass (PDL dependent) --------
__global__ void __launch_bounds__(TB)
k_edge2(const int* __restrict__ ei, const float* __restrict__ b1,
        const float* __restrict__ W2, const float* __restrict__ as2,
        const float* __restrict__ ad2) {
    int t = blockIdx.x * TB + threadIdx.x;
    int s, d;                                        // preamble: inputs only
    if (t < EE) { s = __ldg(ei + t); d = __ldg(ei + EE + t); } else { s = t - EE; d = s; }
    float b1r[3], W2r[9], s2[3], d2[3];
#pragma unroll
    for (int k = 0; k < 3; k++) { b1r[k] = __ldg(b1 + k); s2[k] = __ldg(as2 + k); d2[k] = __ldg(ad2 + k); }
#pragma unroll
    for (int k = 0; k < 9; k++) W2r[k] = __ldg(W2 + k);

    cudaGridDependencySynchronize();                 // wait for k_edge1's atomics

    float zS[3], zD[3];
    z2_of(s, b1r, W2r, zS);
    z2_of(d, b1r, W2r, zD);
    float zs = zS[0]*s2[0] + zS[1]*s2[1] + zS[2]*s2[2];
    float zd = zD[0]*d2[0] + zD[1]*d2[1] + zD[2]*d2[2];
    float w = __expf(leaky(zs + zd));
    atomicAdd(&g_nB[d].x, w * zS[0]);
    atomicAdd(&g_nB[d].y, w * zS[1]);
    atomicAdd(&g_nB[d].z, w * zS[2]);
    atomicAdd(&g_nB[d].w, w);
}

__device__ __forceinline__ float z3_of(int n, const float* b2r, const float* W3r) {
    float4 a = g_nB[n];
    float inv = 1.0f / (a.w + 1e-16f);
    return relu(a.x * inv + b2r[0]) * W3r[0]
         + relu(a.y * inv + b2r[1]) * W3r[1]
         + relu(a.z * inv + b2r[2]) * W3r[2];
}

// -------- kernel 3: layer-3 edge pass (PDL); LAST block (1024 thr) does softmax --------
__global__ void __launch_bounds__(TB)
k_edge3(const int* __restrict__ ei, const float* __restrict__ b2,
        const float* __restrict__ W3, const float* __restrict__ as3,
        const float* __restrict__ ad3, const float* __restrict__ b3,
        const float* __restrict__ phi1, const float* __restrict__ phi2,
        float* __restrict__ out) {
    int t = blockIdx.x * TB + threadIdx.x;
    int s, d;
    if (t < EE) { s = __ldg(ei + t); d = __ldg(ei + EE + t); } else { s = t - EE; d = s; }
    float b2r[3], W3r[3];
#pragma unroll
    for (int k = 0; k < 3; k++) { b2r[k] = __ldg(b2 + k); W3r[k] = __ldg(W3 + k); }
    float a3s = __ldg(as3), a3d = __ldg(ad3);

    cudaGridDependencySynchronize();                 // wait for k_edge2's atomics

    float zS = z3_of(s, b2r, W3r);
    float zD = z3_of(d, b2r, W3r);
    float w = __expf(leaky(zS * a3s + zD * a3d));
    atomicAdd(&g_n3[d].x, w * zS);
    atomicAdd(&g_n3[d].y, w);

    // ---- last-finishing block: node softmax + argmax(start) + p12, 1024 threads ----
    __shared__ unsigned isLast;
    __threadfence();
    __syncthreads();
    if (threadIdx.x == 0)
        isLast = (atomicAdd(&g_done3, 1u) == (unsigned)(gridDim.x - 1)) ? 1u : 0u;
    __syncthreads();
    if (!isLast) return;

    {
        const int tid = threadIdx.x;                 // 1024 threads, 4 nodes each
        __shared__ float sred[32];
        __shared__ unsigned long long skey[32];
        __shared__ float s_sum;
        float b = __ldg(b3);
        float wv[4];
        float lsum = 0.f;
#pragma unroll
        for (int r = 0; r < 4; r++) {
            int i = r * TB + tid;
            float2 a = __ldcg(&g_n3[i]);
            float o = a.x / (a.y + 1e-16f) + b;
            wv[r] = __expf(o);
            lsum += wv[r];
        }
#pragma unroll
        for (int off = 16; off > 0; off >>= 1) lsum += __shfl_down_sync(0xFFFFFFFFu, lsum, off);
        if ((tid & 31) == 0) sred[tid >> 5] = lsum;
        __syncthreads();
        if (tid < 32) {
            float v = sred[tid];
#pragma unroll
            for (int off = 16; off > 0; off >>= 1) v += __shfl_down_sync(0xFFFFFFFFu, v, off);
            if (tid == 0) s_sum = v;
        }
        __syncthreads();
        float inv = 1.0f / s_sum;

        unsigned long long lkey = 0ull;
#pragma unroll
        for (int r = 0; r < 4; r++) {
            int i = r * TB + tid;
            float xo = wv[r] * inv;
            out[i]  = xo;
            g_xf[i] = xo;
            unsigned long long k =
                ((unsigned long long)fenc(xo) << 32) | (unsigned long long)(0xFFFFFFFFu - (unsigned)i);
            if (k > lkey) lkey = k;
        }
#pragma unroll
        for (int off = 16; off > 0; off >>= 1) {
            unsigned long long o2 = __shfl_down_sync(0xFFFFFFFFu, lkey, off);
            if (o2 > lkey) lkey = o2;
        }
        if ((tid & 31) == 0) skey[tid >> 5] = lkey;
        __syncthreads();
        if (tid < 32) {
            unsigned long long v = skey[tid];
#pragma unroll
            for (int off = 16; off > 0; off >>= 1) {
                unsigned long long o2 = __shfl_down_sync(0xFFFFFFFFu, v, off);
                if (o2 > v) v = o2;
            }
            if (tid == 0) g_start = (int)(0xFFFFFFFFu - (unsigned)(v & 0xFFFFFFFFull));
        } else if (tid < 64) {                        // warp 1: p12 in parallel
            int l = tid - 32;
            float p = 0.f;
#pragma unroll
            for (int k = 0; k < 4; k++) p += __ldg(phi1 + l + 32 * k) * __ldg(phi2 + l + 32 * k);
#pragma unroll
            for (int off = 16; off > 0; off >>= 1) p += __shfl_down_sync(0xFFFFFFFFu, p, off);
            if (l == 0) g_p12 = p;
        }
        if (tid == 0) g_done3 = 0;                   // reset for next launch
    }
}

// -------- kernel 4 (PDL): chain keys + zeroing; LAST block (1024 thr) does the walk --------
__global__ void __launch_bounds__(TB)
k_ckey(const int* __restrict__ ei, float* __restrict__ out, int out_size) {
    int j = blockIdx.x * TB + threadIdx.x;           // 0..EE-1 exactly
    int s = __ldg(ei + j), d = __ldg(ei + EE + j);

    cudaGridDependencySynchronize();                 // wait for k_edge3 (incl. softmax tail)

    {
        const float scale = 1.0f / sqrtf(128.0f);
        float t = ((g_p12 * g_xf[s]) * g_xf[d]) * scale;   // match reference mul order
        float sc = tanhf(t);                                // CONST == 1.0
        unsigned long long key =
            ((unsigned long long)fenc(sc) << 32) | (unsigned long long)(0xFFFFFFFFu - (unsigned)j);
        atomicMax(&g_ckey[s], key);
    }
    // restore all-zeros invariant on dead accumulators (vectorized)
    if (j < NN)                ((float4*)g_nA)[j] = make_float4(0.f, 0.f, 0.f, 0.f);
    else if (j < 2 * NN)       ((float4*)g_nB)[j - NN] = make_float4(0.f, 0.f, 0.f, 0.f);
    else if (j < 3 * NN)       ((float2*)g_n3)[j - 2 * NN] = make_float2(0.f, 0.f);

    // ---- last-finishing block: resolve next[], pointer-double the walk ----
    __shared__ unsigned isLast;
    __threadfence();
    __syncthreads();
    if (threadIdx.x == 0)
        isLast = (atomicAdd(&g_doneC, 1u) == (unsigned)(gridDim.x - 1)) ? 1u : 0u;
    __syncthreads();
    if (!isLast) return;

    {
        __shared__ int A[NN];
        __shared__ int B[NN];
        const int tid = threadIdx.x;                 // 1024 threads, 4 each
#pragma unroll
        for (int r = 0; r < 4; r++) {
            int i = r * TB + tid;
            unsigned long long key = __ldcg(&g_ckey[i]);
            g_ckey[i] = 0ull;                        // reset for next launch
            int jj = key ? (int)(0xFFFFFFFFu - (unsigned)(key & 0xFFFFFFFFull)) : 0;
            A[i] = __ldg(ei + EE + jj);
        }
        __syncthreads();
        int* pa = A; int* pb = B;
        for (int it = 0; it < 12; it++) {            // next^(2^12) = next^4096, ping-pong
#pragma unroll
            for (int r = 0; r < 4; r++) { int i = r * TB + tid; pb[i] = pa[pa[i]]; }
            __syncthreads();
            int* tmp = pa; pa = pb; pb = tmp;
        }
        if (tid == 0) {
            if (out_size > NN) out[NN] = (float)pa[g_start];
            g_doneC = 0;                             // reset for next launch
        }
    }
}

// ---------------- launch ----------------
extern "C" void kernel_launch(void* const* d_in, const int* in_sizes, int n_in,
                              void* d_out, int out_size) {
    const float* x    = (const float*)d_in[0];
    const int*   ei   = (const int*)  d_in[1];
    const float* W1   = (const float*)d_in[2];
    const float* as1  = (const float*)d_in[3];
    const float* ad1  = (const float*)d_in[4];
    const float* b1   = (const float*)d_in[5];
    const float* W2   = (const float*)d_in[6];
    const float* as2  = (const float*)d_in[7];
    const float* ad2  = (const float*)d_in[8];
    const float* b2   = (const float*)d_in[9];
    const float* W3   = (const float*)d_in[10];
    const float* as3  = (const float*)d_in[11];
    const float* ad3  = (const float*)d_in[12];
    const float* b3   = (const float*)d_in[13];
    const float* phi1 = (const float*)d_in[14];
    const float* phi2 = (const float*)d_in[15];
    float* out = (float*)d_out;

    // kernel 1: plain launch
    k_edge1<<<NB_E, TB>>>(x, ei, W1, as1, ad1);

    // kernels 2-4: PDL so launch/preamble overlaps the predecessor's tail
    cudaLaunchAttribute attr[1];
    attr[0].id = cudaLaunchAttributeProgrammaticStreamSerialization;
    attr[0].val.programmaticStreamSerializationAllowed = 1;

    cudaLaunchConfig_t cfg = {};
    cfg.blockDim = dim3(TB, 1, 1);
    cfg.attrs = attr;
    cfg.numAttrs = 1;

    cfg.gridDim = dim3(NB_E, 1, 1);
    cudaLaunchKernelEx(&cfg, k_edge2, ei, b1, W2, as2, ad2);
    cudaLaunchKernelEx(&cfg, k_edge3, ei, b2, W3, as3, ad3, b3, phi1, phi2, out);

    cfg.gridDim = dim3(NB_C, 1, 1);
    cudaLaunchKernelEx(&cfg, k_ckey, ei, out, out_size);
}